// round 5
// baseline (speedup 1.0000x reference)
#include <cuda_runtime.h>
#include <cuda_bf16.h>

// Problem constants
#define T_STEPS 1024
#define NK      16
#define HID     20
#define GATES   80
#define CELLS   1024
#define WARPS_PER_CTA 8
#define NTHREADS (WARPS_PER_CTA * 32)   // 256
#define CTAS    (CELLS / WARPS_PER_CTA) // 128
#define XSTRIDE 48                      // NK*3 floats per time step

__device__ float g_y[CELLS + 1];
__device__ int   g_done;

typedef unsigned long long ull;

// ---------- packed f32x2 + MUFU helpers ----------
__device__ __forceinline__ ull pk2(float lo, float hi) {
    ull r;
    asm("mov.b64 %0, {%1, %2};" : "=l"(r) : "f"(lo), "f"(hi));
    return r;
}
__device__ __forceinline__ void upk2(ull v, float& lo, float& hi) {
    asm("mov.b64 {%0, %1}, %2;" : "=f"(lo), "=f"(hi) : "l"(v));
}
__device__ __forceinline__ void fma2(ull& d, ull a, ull b) {
    asm("fma.rn.f32x2 %0, %1, %2, %0;" : "+l"(d) : "l"(a), "l"(b));
}
__device__ __forceinline__ ull add2(ull a, ull b) {
    ull r;
    asm("add.rn.f32x2 %0, %1, %2;" : "=l"(r) : "l"(a), "l"(b));
    return r;
}
__device__ __forceinline__ float ex2f(float x) {
    float r; asm("ex2.approx.f32 %0, %1;" : "=f"(r) : "f"(x)); return r;
}
__device__ __forceinline__ float rcpf(float x) {
    float r; asm("rcp.approx.f32 %0, %1;" : "=f"(r) : "f"(x)); return r;
}
// HW tanh (MUFU.TANH)
__device__ __forceinline__ float tanha(float x) {
    float r; asm("tanh.approx.f32 %0, %1;" : "=f"(r) : "f"(x)); return r;
}
// precise tanh for the head (off the hot loop)
__device__ __forceinline__ float tanhx(float x) {
    float e = ex2f(2.8853900817779268f * x);
    return fmaf(-2.0f, rcpf(e + 1.0f), 1.0f);
}

// ---------- fused kernel: scan + head + (last CTA) softmax ----------
__global__ void __launch_bounds__(NTHREADS, 1)
lstm_fused(const float* __restrict__ inp,   // [B,T,K,I]
           const float* __restrict__ w,     // [K*B+1]
           const float* __restrict__ W_ih,  // [K,4H,I]
           const float* __restrict__ W_hh,  // [K,4H,H]
           const float* __restrict__ b_ih,  // [K,4H]
           const float* __restrict__ b_hh,  // [K,4H]
           const float* __restrict__ conv_w,// [H+1]
           const float* __restrict__ conv_b,// scalar
           float* __restrict__ out)         // [1025]
{
    __shared__ float red[32];
    __shared__ int   s_last;

    const int tid  = threadIdx.x;
    const int wid  = tid >> 5;
    const int lane = tid & 31;
    const int cell = blockIdx.x * WARPS_PER_CTA + wid;   // = k*64 + b
    const int k    = cell >> 6;
    const int b    = cell & 63;
    const int ju   = (lane < HID) ? lane : (HID - 1);    // lanes 20..31 duplicate unit 19

    // ---- preload weights; fold sigmoid's 0.5 pre-scale into gates i,f,o (g unscaled) ----
    ull   whh[4][10];
    float wx[4][3], bs[4];
#pragma unroll
    for (int g = 0; g < 4; ++g) {
        const float sc  = (g == 2) ? 1.0f : 0.5f;
        const int   row = k * GATES + g * HID + ju;
        const float* wr = W_hh + (size_t)row * HID;
#pragma unroll
        for (int m = 0; m < 10; ++m) {
            float2 v = *reinterpret_cast<const float2*>(wr + 2 * m);
            whh[g][m] = pk2(v.x * sc, v.y * sc);
        }
        wx[g][0] = W_ih[(size_t)row * 3 + 0] * sc;
        wx[g][1] = W_ih[(size_t)row * 3 + 1] * sc;
        wx[g][2] = W_ih[(size_t)row * 3 + 2] * sc;
        bs[g]    = (b_ih[row] + b_hh[row]) * sc;
    }

    // ---- init state (h lives one element per lane; no smem in the loop) ----
    float c = 0.0f, h = 0.0f;

    const float* ip = inp + (size_t)b * (T_STEPS * XSTRIDE) + k * 3;

    // x pipeline (distance-2): xa = raw x(t+1), xb = raw x(t+2); ps = proj(x(t))
    float xa0 = ip[XSTRIDE + 0], xa1 = ip[XSTRIDE + 1], xa2 = ip[XSTRIDE + 2];
    float xb0 = ip[2 * XSTRIDE + 0], xb1 = ip[2 * XSTRIDE + 1], xb2 = ip[2 * XSTRIDE + 2];
    float ps0, ps1, ps2, ps3;
    {
        const float x0 = ip[0], x1 = ip[1], x2 = ip[2];
        ps0 = fmaf(wx[0][2], x2, fmaf(wx[0][1], x1, fmaf(wx[0][0], x0, bs[0])));
        ps1 = fmaf(wx[1][2], x2, fmaf(wx[1][1], x1, fmaf(wx[1][0], x0, bs[1])));
        ps2 = fmaf(wx[2][2], x2, fmaf(wx[2][1], x1, fmaf(wx[2][0], x0, bs[2])));
        ps3 = fmaf(wx[3][2], x2, fmaf(wx[3][1], x1, fmaf(wx[3][0], x0, bs[3])));
    }

#pragma unroll 1
    for (int t = 0; t < T_STEPS; ++t) {
        // prefetch raw x(t+3), consumed as proj two iterations from now
        int tp = t + 3; if (tp > T_STEPS - 1) tp = T_STEPS - 1;
        const float* ipn = ip + (size_t)tp * XSTRIDE;
        const float xc0 = ipn[0], xc1 = ipn[1], xc2 = ipn[2];

        // recurrent matvec: h-pairs built by warp shuffles (no smem, no syncwarp)
        ull a0e = pk2(ps0, 0.0f), a0o = 0ULL;
        ull a1e = pk2(ps1, 0.0f), a1o = 0ULL;
        ull a2e = pk2(ps2, 0.0f), a2o = 0ULL;
        ull a3e = pk2(ps3, 0.0f), a3o = 0ULL;

#pragma unroll
        for (int q = 0; q < 5; ++q) {
            const float e0 = __shfl_sync(0xffffffffu, h, 4 * q + 0);
            const float e1 = __shfl_sync(0xffffffffu, h, 4 * q + 1);
            const float e2 = __shfl_sync(0xffffffffu, h, 4 * q + 2);
            const float e3 = __shfl_sync(0xffffffffu, h, 4 * q + 3);
            const ull p0 = pk2(e0, e1);
            const ull p1 = pk2(e2, e3);
            fma2(a0e, whh[0][2*q],   p0);
            fma2(a1e, whh[1][2*q],   p0);
            fma2(a2e, whh[2][2*q],   p0);
            fma2(a3e, whh[3][2*q],   p0);
            fma2(a0o, whh[0][2*q+1], p1);
            fma2(a1o, whh[1][2*q+1], p1);
            fma2(a2o, whh[2][2*q+1], p1);
            fma2(a3o, whh[3][2*q+1], p1);
        }

        // proj(t+1) from xa — independent work filling latency shadows
        const float n0 = fmaf(wx[0][2], xa2, fmaf(wx[0][1], xa1, fmaf(wx[0][0], xa0, bs[0])));
        const float n1 = fmaf(wx[1][2], xa2, fmaf(wx[1][1], xa1, fmaf(wx[1][0], xa0, bs[1])));
        const float n2 = fmaf(wx[2][2], xa2, fmaf(wx[2][1], xa1, fmaf(wx[2][0], xa0, bs[2])));
        const float n3 = fmaf(wx[3][2], xa2, fmaf(wx[3][1], xa1, fmaf(wx[3][0], xa0, bs[3])));

        float lo, hi, gi, gf, gg, go;
        upk2(add2(a0e, a0o), lo, hi); gi = lo + hi;
        upk2(add2(a1e, a1o), lo, hi); gf = lo + hi;
        upk2(add2(a2e, a2o), lo, hi); gg = lo + hi;
        upk2(add2(a3e, a3o), lo, hi); go = lo + hi;

        // gates (0.5 pre-scale folded into weights for i,f,o)
        const float si = fmaf(0.5f, tanha(gi), 0.5f);
        const float sf = fmaf(0.5f, tanha(gf), 0.5f);
        const float tg = tanha(gg);
        const float so = fmaf(0.5f, tanha(go), 0.5f);
        c = fmaf(sf, c, si * tg);
        h = so * tanha(c);

        ps0 = n0; ps1 = n1; ps2 = n2; ps3 = n3;
        xa0 = xb0; xa1 = xb1; xa2 = xb2;
        xb0 = xc0; xb1 = xc1; xb2 = xc2;
    }

    // ---- head: y = tanh( dot(h, conv_w[0:20]) + w[1+cell]*conv_w[20] + conv_b ) ----
    float contrib = (lane < HID) ? h * conv_w[lane] : 0.0f;
#pragma unroll
    for (int o = 16; o; o >>= 1)
        contrib += __shfl_xor_sync(0xffffffffu, contrib, o);
    if (lane == 0) {
        float yv = tanhx(contrib + w[1 + cell] * conv_w[HID] + conv_b[0]);
        g_y[1 + cell] = yv;
        if (cell == 0) g_y[0] = 1.0f;   // prepended cash constant
    }

    // ---- completion protocol (threadFenceReduction pattern) ----
    __threadfence();
    __syncthreads();
    if (tid == 0) {
        int prev = atomicAdd(&g_done, 1);
        s_last = (prev == CTAS - 1);
    }
    __syncthreads();
    if (!s_last) return;
    if (tid == 0) g_done = 0;   // reset for next graph replay

    // ---- last CTA: softmax over y[0..1024] (256 threads, 4 values each + 1 extra) ----
    float v[4];
#pragma unroll
    for (int q = 0; q < 4; ++q) v[q] = __ldcg(&g_y[tid + 256 * q]);
    float vx = (tid == 0) ? __ldcg(&g_y[CELLS]) : -3.0e38f;

    // block max
    float m = fmaxf(fmaxf(fmaxf(v[0], v[1]), fmaxf(v[2], v[3])), vx);
#pragma unroll
    for (int o = 16; o; o >>= 1) m = fmaxf(m, __shfl_xor_sync(0xffffffffu, m, o));
    if (lane == 0) red[wid] = m;
    __syncthreads();
    if (wid == 0) {
        float mm = (lane < WARPS_PER_CTA) ? red[lane] : -3.0e38f;
#pragma unroll
        for (int o = 4; o; o >>= 1) mm = fmaxf(mm, __shfl_xor_sync(0xffffffffu, mm, o));
        if (lane == 0) red[0] = mm;
    }
    __syncthreads();
    const float M = red[0];
    __syncthreads();

    float e[4];
#pragma unroll
    for (int q = 0; q < 4; ++q) e[q] = ex2f((v[q] - M) * 1.4426950408889634f);
    float ex = (tid == 0) ? ex2f((vx - M) * 1.4426950408889634f) : 0.0f;

    // block sum
    float s = e[0] + e[1] + e[2] + e[3] + ex;
#pragma unroll
    for (int o = 16; o; o >>= 1) s += __shfl_xor_sync(0xffffffffu, s, o);
    if (lane == 0) red[wid] = s;
    __syncthreads();
    if (wid == 0) {
        float ss = (lane < WARPS_PER_CTA) ? red[lane] : 0.0f;
#pragma unroll
        for (int o = 4; o; o >>= 1) ss += __shfl_xor_sync(0xffffffffu, ss, o);
        if (lane == 0) red[0] = ss;
    }
    __syncthreads();
    const float inv = rcpf(red[0]);

#pragma unroll
    for (int q = 0; q < 4; ++q) out[tid + 256 * q] = e[q] * inv;
    if (tid == 0) out[CELLS] = ex * inv;
}

extern "C" void kernel_launch(void* const* d_in, const int* in_sizes, int n_in,
                              void* d_out, int out_size)
{
    const float* inp    = (const float*)d_in[0];
    const float* w      = (const float*)d_in[1];
    const float* W_ih   = (const float*)d_in[2];
    const float* W_hh   = (const float*)d_in[3];
    const float* b_ih   = (const float*)d_in[4];
    const float* b_hh   = (const float*)d_in[5];
    const float* conv_w = (const float*)d_in[6];
    const float* conv_b = (const float*)d_in[7];
    float* out = (float*)d_out;

    lstm_fused<<<CTAS, NTHREADS>>>(inp, w, W_ih, W_hh, b_ih, b_hh,
                                   conv_w, conv_b, out);
}

// round 7
// speedup vs baseline: 1.1499x; 1.1499x over previous
#include <cuda_runtime.h>
#include <cuda_bf16.h>

// Problem constants
#define T_STEPS 1024
#define NK      16
#define HID     20
#define GATES   80
#define CELLS   1024
#define WARPS_PER_CTA 8
#define NTHREADS (WARPS_PER_CTA * 32)   // 256
#define CTAS    (CELLS / WARPS_PER_CTA) // 128
#define ROWF    32                      // padded hbuf row (128B)
#define XSTRIDE 48                      // NK*3 floats per time step

__device__ float g_y[CELLS + 1];
__device__ int   g_done;

typedef unsigned long long ull;

// ---------- packed f32x2 + MUFU helpers ----------
__device__ __forceinline__ ull pk2(float lo, float hi) {
    ull r;
    asm("mov.b64 %0, {%1, %2};" : "=l"(r) : "f"(lo), "f"(hi));
    return r;
}
__device__ __forceinline__ void upk2(ull v, float& lo, float& hi) {
    asm("mov.b64 {%0, %1}, %2;" : "=f"(lo), "=f"(hi) : "l"(v));
}
__device__ __forceinline__ void fma2(ull& d, ull a, ull b) {
    asm("fma.rn.f32x2 %0, %1, %2, %0;" : "+l"(d) : "l"(a), "l"(b));
}
__device__ __forceinline__ ull add2(ull a, ull b) {
    ull r;
    asm("add.rn.f32x2 %0, %1, %2;" : "=l"(r) : "l"(a), "l"(b));
    return r;
}
__device__ __forceinline__ float ex2f(float x) {
    float r; asm("ex2.approx.f32 %0, %1;" : "=f"(r) : "f"(x)); return r;
}
__device__ __forceinline__ float rcpf(float x) {
    float r; asm("rcp.approx.f32 %0, %1;" : "=f"(r) : "f"(x)); return r;
}
// HW tanh (MUFU.TANH)
__device__ __forceinline__ float tanha(float x) {
    float r; asm("tanh.approx.f32 %0, %1;" : "=f"(r) : "f"(x)); return r;
}
// precise tanh for the head (off the hot loop)
__device__ __forceinline__ float tanhx(float x) {
    float e = ex2f(2.8853900817779268f * x);
    return fmaf(-2.0f, rcpf(e + 1.0f), 1.0f);
}

// ---------- fused kernel: scan + head + (last CTA) softmax ----------
__global__ void __launch_bounds__(NTHREADS, 1)
lstm_fused(const float* __restrict__ inp,   // [B,T,K,I]
           const float* __restrict__ w,     // [K*B+1]
           const float* __restrict__ W_ih,  // [K,4H,I]
           const float* __restrict__ W_hh,  // [K,4H,H]
           const float* __restrict__ b_ih,  // [K,4H]
           const float* __restrict__ b_hh,  // [K,4H]
           const float* __restrict__ conv_w,// [H+1]
           const float* __restrict__ conv_b,// scalar
           float* __restrict__ out)         // [1025]
{
    __shared__ __align__(16) float hbuf[WARPS_PER_CTA][ROWF];
    __shared__ float red[32];
    __shared__ int   s_last;

    const int tid  = threadIdx.x;
    const int wid  = tid >> 5;
    const int lane = tid & 31;
    const int cell = blockIdx.x * WARPS_PER_CTA + wid;   // = k*64 + b
    const int k    = cell >> 6;
    const int b    = cell & 63;
    const int ju   = (lane < HID) ? lane : (HID - 1);    // lanes 20..31 duplicate unit 19

    // ---- preload weights; fold sigmoid's 0.5 pre-scale into gates i,f,o (g unscaled) ----
    ull   whh[4][10];
    float wx[4][3], bs[4];
#pragma unroll
    for (int g = 0; g < 4; ++g) {
        const float sc  = (g == 2) ? 1.0f : 0.5f;
        const int   row = k * GATES + g * HID + ju;
        const float* wr = W_hh + (size_t)row * HID;
#pragma unroll
        for (int m = 0; m < 10; ++m) {
            float2 v = *reinterpret_cast<const float2*>(wr + 2 * m);
            whh[g][m] = pk2(v.x * sc, v.y * sc);
        }
        wx[g][0] = W_ih[(size_t)row * 3 + 0] * sc;
        wx[g][1] = W_ih[(size_t)row * 3 + 1] * sc;
        wx[g][2] = W_ih[(size_t)row * 3 + 2] * sc;
        bs[g]    = (b_ih[row] + b_hh[row]) * sc;
    }

    const unsigned haddr = (unsigned)__cvta_generic_to_shared(&hbuf[wid][0]);

    // ---- init state ----
    if (lane < HID) hbuf[wid][lane] = 0.0f;
    float c = 0.0f, h = 0.0f;

    const float* ip = inp + (size_t)b * (T_STEPS * XSTRIDE) + k * 3;

    // x pipeline (distance-2): xa = raw x(t+1), xb = raw x(t+2); ps = proj(x(t))
    float xa0 = ip[XSTRIDE + 0], xa1 = ip[XSTRIDE + 1], xa2 = ip[XSTRIDE + 2];
    float xb0 = ip[2 * XSTRIDE + 0], xb1 = ip[2 * XSTRIDE + 1], xb2 = ip[2 * XSTRIDE + 2];
    float ps0, ps1, ps2, ps3;
    {
        const float x0 = ip[0], x1 = ip[1], x2 = ip[2];
        ps0 = fmaf(wx[0][2], x2, fmaf(wx[0][1], x1, fmaf(wx[0][0], x0, bs[0])));
        ps1 = fmaf(wx[1][2], x2, fmaf(wx[1][1], x1, fmaf(wx[1][0], x0, bs[1])));
        ps2 = fmaf(wx[2][2], x2, fmaf(wx[2][1], x1, fmaf(wx[2][0], x0, bs[2])));
        ps3 = fmaf(wx[3][2], x2, fmaf(wx[3][1], x1, fmaf(wx[3][0], x0, bs[3])));
    }
    __syncwarp();

    // ---- de-phase: odd warps burn ~190 dependent cycles ONCE so the two
    // warps sharing each SMSP interleave their latency gaps instead of
    // stalling in lockstep (both warps otherwise have identical timing).
    if (wid & 1) {
        float d0 = 1.0f;
#pragma unroll
        for (int i = 0; i < 48; ++i)
            asm volatile("add.f32 %0, %0, %0;" : "+f"(d0));
    }

#pragma unroll 1
    for (int t = 0; t < T_STEPS; ++t) {
        // prefetch raw x(t+3), consumed as proj two iterations from now
        int tp = t + 3; if (tp > T_STEPS - 1) tp = T_STEPS - 1;
        const float* ipn = ip + (size_t)tp * XSTRIDE;
        const float xc0 = ipn[0], xc1 = ipn[1], xc2 = ipn[2];

        // recurrent matvec: 2 partial chains per gate (depth 5 each), seeded with proj(t)
        ull a0e = pk2(ps0, 0.0f), a0o = 0ULL;
        ull a1e = pk2(ps1, 0.0f), a1o = 0ULL;
        ull a2e = pk2(ps2, 0.0f), a2o = 0ULL;
        ull a3e = pk2(ps3, 0.0f), a3o = 0ULL;

#pragma unroll
        for (int q = 0; q < 5; ++q) {
            ull p0, p1;   // pairs (h[4q],h[4q+1]) and (h[4q+2],h[4q+3])
            asm volatile("ld.shared.v2.b64 {%0, %1}, [%2];"
                         : "=l"(p0), "=l"(p1) : "r"(haddr + 16u * q));
            fma2(a0e, whh[0][2*q],   p0);
            fma2(a1e, whh[1][2*q],   p0);
            fma2(a2e, whh[2][2*q],   p0);
            fma2(a3e, whh[3][2*q],   p0);
            fma2(a0o, whh[0][2*q+1], p1);
            fma2(a1o, whh[1][2*q+1], p1);
            fma2(a2o, whh[2][2*q+1], p1);
            fma2(a3o, whh[3][2*q+1], p1);
        }

        // proj(t+1) from xa — independent work that fills LDS/FMA latency shadows
        const float n0 = fmaf(wx[0][2], xa2, fmaf(wx[0][1], xa1, fmaf(wx[0][0], xa0, bs[0])));
        const float n1 = fmaf(wx[1][2], xa2, fmaf(wx[1][1], xa1, fmaf(wx[1][0], xa0, bs[1])));
        const float n2 = fmaf(wx[2][2], xa2, fmaf(wx[2][1], xa1, fmaf(wx[2][0], xa0, bs[2])));
        const float n3 = fmaf(wx[3][2], xa2, fmaf(wx[3][1], xa1, fmaf(wx[3][0], xa0, bs[3])));

        float lo, hi, gi, gf, gg, go;
        upk2(add2(a0e, a0o), lo, hi); gi = lo + hi;
        upk2(add2(a1e, a1o), lo, hi); gf = lo + hi;
        upk2(add2(a2e, a2o), lo, hi); gg = lo + hi;
        upk2(add2(a3e, a3o), lo, hi); go = lo + hi;

        // gates (0.5 pre-scale folded into weights for i,f,o)
        const float si = fmaf(0.5f, tanha(gi), 0.5f);
        const float sf = fmaf(0.5f, tanha(gf), 0.5f);
        const float tg = tanha(gg);
        const float so = fmaf(0.5f, tanha(go), 0.5f);
        c = fmaf(sf, c, si * tg);
        h = so * tanha(c);

        if (lane < HID) hbuf[wid][lane] = h;
        __syncwarp();

        ps0 = n0; ps1 = n1; ps2 = n2; ps3 = n3;
        xa0 = xb0; xa1 = xb1; xa2 = xb2;
        xb0 = xc0; xb1 = xc1; xb2 = xc2;
    }

    // ---- head: y = tanh( dot(h, conv_w[0:20]) + w[1+cell]*conv_w[20] + conv_b ) ----
    float contrib = (lane < HID) ? h * conv_w[lane] : 0.0f;
#pragma unroll
    for (int o = 16; o; o >>= 1)
        contrib += __shfl_xor_sync(0xffffffffu, contrib, o);
    if (lane == 0) {
        float yv = tanhx(contrib + w[1 + cell] * conv_w[HID] + conv_b[0]);
        g_y[1 + cell] = yv;
        if (cell == 0) g_y[0] = 1.0f;   // prepended cash constant
    }

    // ---- completion protocol (threadFenceReduction pattern) ----
    __threadfence();
    __syncthreads();
    if (tid == 0) {
        int prev = atomicAdd(&g_done, 1);
        s_last = (prev == CTAS - 1);
    }
    __syncthreads();
    if (!s_last) return;
    if (tid == 0) g_done = 0;   // reset for next graph replay

    // ---- last CTA: softmax over y[0..1024] (256 threads, 4 values each + 1 extra) ----
    float v[4];
#pragma unroll
    for (int q = 0; q < 4; ++q) v[q] = __ldcg(&g_y[tid + 256 * q]);
    float vx = (tid == 0) ? __ldcg(&g_y[CELLS]) : -3.0e38f;

    // block max
    float m = fmaxf(fmaxf(fmaxf(v[0], v[1]), fmaxf(v[2], v[3])), vx);
#pragma unroll
    for (int o = 16; o; o >>= 1) m = fmaxf(m, __shfl_xor_sync(0xffffffffu, m, o));
    if (lane == 0) red[wid] = m;
    __syncthreads();
    if (wid == 0) {
        float mm = (lane < WARPS_PER_CTA) ? red[lane] : -3.0e38f;
#pragma unroll
        for (int o = 4; o; o >>= 1) mm = fmaxf(mm, __shfl_xor_sync(0xffffffffu, mm, o));
        if (lane == 0) red[0] = mm;
    }
    __syncthreads();
    const float M = red[0];
    __syncthreads();

    float e[4];
#pragma unroll
    for (int q = 0; q < 4; ++q) e[q] = ex2f((v[q] - M) * 1.4426950408889634f);
    float ex = (tid == 0) ? ex2f((vx - M) * 1.4426950408889634f) : 0.0f;

    // block sum
    float s = e[0] + e[1] + e[2] + e[3] + ex;
#pragma unroll
    for (int o = 16; o; o >>= 1) s += __shfl_xor_sync(0xffffffffu, s, o);
    if (lane == 0) red[wid] = s;
    __syncthreads();
    if (wid == 0) {
        float ss = (lane < WARPS_PER_CTA) ? red[lane] : 0.0f;
#pragma unroll
        for (int o = 4; o; o >>= 1) ss += __shfl_xor_sync(0xffffffffu, ss, o);
        if (lane == 0) red[0] = ss;
    }
    __syncthreads();
    const float inv = rcpf(red[0]);

#pragma unroll
    for (int q = 0; q < 4; ++q) out[tid + 256 * q] = e[q] * inv;
    if (tid == 0) out[CELLS] = ex * inv;
}

extern "C" void kernel_launch(void* const* d_in, const int* in_sizes, int n_in,
                              void* d_out, int out_size)
{
    const float* inp    = (const float*)d_in[0];
    const float* w      = (const float*)d_in[1];
    const float* W_ih   = (const float*)d_in[2];
    const float* W_hh   = (const float*)d_in[3];
    const float* b_ih   = (const float*)d_in[4];
    const float* b_hh   = (const float*)d_in[5];
    const float* conv_w = (const float*)d_in[6];
    const float* conv_b = (const float*)d_in[7];
    float* out = (float*)d_out;

    lstm_fused<<<CTAS, NTHREADS>>>(inp, w, W_ih, W_hh, b_ih, b_hh,
                                   conv_w, conv_b, out);
}